// round 2
// baseline (speedup 1.0000x reference)
#include <cuda_runtime.h>
#include <cstdint>

#define NN   200000
#define DIM  20
#define EE   6400000
#define ITERS 3

// Persistent scratch (allocations banned; __device__ globals are the workaround)
__device__ __align__(16) float g_h[(size_t)NN * DIM];
__device__ __align__(16) float g_x[(size_t)NN * DIM];
// Compacted edge lists: bucket0 = maxd<=1 (all 3 iters), bucket1 = maxd==2
// (iters 0-1), bucket2 = maxd==3 (iter 0 only). maxd==4 edges never used.
__device__ __align__(16) int2 g_e0[EE];
__device__ __align__(16) int2 g_e1[EE];
__device__ __align__(16) int2 g_e2[EE];
__device__ int g_cnt[3];

// ---------------------------------------------------------------------------
// init: copy input h into scratch, zero x, zero bucket counters
// ---------------------------------------------------------------------------
__global__ void init_kernel(const float* __restrict__ h_in) {
    int i = blockIdx.x * blockDim.x + threadIdx.x;
    if (i < 3) g_cnt[i] = 0;
    const int n4 = NN * DIM / 4;
    if (i < n4) {
        reinterpret_cast<float4*>(g_h)[i] = reinterpret_cast<const float4*>(h_in)[i];
        reinterpret_cast<float4*>(g_x)[i] = make_float4(0.f, 0.f, 0.f, 0.f);
    }
}

// ---------------------------------------------------------------------------
// compaction: one pass over E edges, bucket by maxd with block aggregation
// ---------------------------------------------------------------------------
#define CTHREADS 512
#define EPT      8
#define CHUNK    (CTHREADS * EPT)   // 4096 edges per block

__global__ void compact_kernel(const int* __restrict__ esrc,
                               const int* __restrict__ edst,
                               const int* __restrict__ depth) {
    __shared__ int s_cnt[3];    // block-local bucket counts / cursors
    __shared__ int s_base[3];   // global base per bucket
    if (threadIdx.x < 3) s_cnt[threadIdx.x] = 0;
    __syncthreads();

    const int start = blockIdx.x * CHUNK;
    int sarr[EPT], darr[EPT];
    int code[EPT];              // 0,1,2 = bucket, 3 = drop
    int cnt[3] = {0, 0, 0};

#pragma unroll
    for (int k = 0; k < EPT; k++) {
        int e = start + threadIdx.x * EPT + k;
        code[k] = 3;
        if (e < EE) {
            int s = __ldg(esrc + e);
            int d = __ldg(edst + e);
            int maxd = max(__ldg(depth + s), __ldg(depth + d));
            if (maxd <= 3) {
                int b = (maxd <= 1) ? 0 : (maxd - 1);
                code[k] = b;
                cnt[b]++;
                sarr[k] = s; darr[k] = d;
            }
        }
    }

    // reserve per-thread ranges within the block
    int toff[3];
#pragma unroll
    for (int b = 0; b < 3; b++)
        toff[b] = cnt[b] ? atomicAdd(&s_cnt[b], cnt[b]) : 0;
    __syncthreads();

    // reserve block range globally
    if (threadIdx.x < 3)
        s_base[threadIdx.x] = atomicAdd(&g_cnt[threadIdx.x], s_cnt[threadIdx.x]);
    __syncthreads();

    int2* lists[3] = { g_e0, g_e1, g_e2 };
    int w[3] = { 0, 0, 0 };
#pragma unroll
    for (int k = 0; k < EPT; k++) {
        int b = code[k];
        if (b < 3) {
            lists[b][s_base[b] + toff[b] + w[b]] = make_int2(sarr[k], darr[k]);
            w[b]++;
        }
    }
}

// ---------------------------------------------------------------------------
// scatter: x[dst] += h[src] over the first nb buckets (persistent grid-stride)
// ---------------------------------------------------------------------------
__device__ __forceinline__ void red_add_v4(float* p, float4 v) {
    unsigned long long ga = (unsigned long long)__cvta_generic_to_global((void*)p);
    asm volatile("red.global.add.v4.f32 [%0], {%1,%2,%3,%4};"
                 :: "l"(ga), "f"(v.x), "f"(v.y), "f"(v.z), "f"(v.w)
                 : "memory");
}

__global__ void scatter_kernel(int nb) {
    const int c0 = g_cnt[0];
    const int c1 = (nb > 1) ? g_cnt[1] : 0;
    const int c2 = (nb > 2) ? g_cnt[2] : 0;
    const int total = c0 + c1 + c2;
    const int stride = gridDim.x * blockDim.x;

    for (int i = blockIdx.x * blockDim.x + threadIdx.x; i < total; i += stride) {
        int2 sd;
        if (i < c0)            sd = g_e0[i];
        else if (i < c0 + c1)  sd = g_e1[i - c0];
        else                   sd = g_e2[i - c0 - c1];

        const float4* hp = reinterpret_cast<const float4*>(g_h + (size_t)sd.x * DIM);
        float4 v0 = hp[0], v1 = hp[1], v2 = hp[2], v3 = hp[3], v4 = hp[4];

        float* xp = g_x + (size_t)sd.y * DIM;
        red_add_v4(xp + 0,  v0);
        red_add_v4(xp + 4,  v1);
        red_add_v4(xp + 8,  v2);
        red_add_v4(xp + 12, v3);
        red_add_v4(xp + 16, v4);
    }
}

// ---------------------------------------------------------------------------
// GRU update per node (fused x re-zeroing)
// ---------------------------------------------------------------------------
struct WParams {
    const float* W[6];   // Wz, Uz, Wr, Ur, Wh, Uh   ([DIM,DIM], row = out)
    const float* B[6];   // bz, buz, br, bur, bh, buh
};

__device__ __forceinline__ float fsigmoid(float v) {
    return 1.f / (1.f + __expf(-v));
}

__global__ void gru_kernel(const int* __restrict__ depth, int thr,
                           WParams p, float* __restrict__ out_final,
                           int clear_x) {
    __shared__ __align__(16) float sW[6 * DIM * DIM];
    __shared__ float sB[6 * DIM];

    for (int t = threadIdx.x; t < 6 * DIM * DIM; t += blockDim.x)
        sW[t] = p.W[t / (DIM * DIM)][t % (DIM * DIM)];
    for (int t = threadIdx.x; t < 6 * DIM; t += blockDim.x)
        sB[t] = p.B[t / DIM][t % DIM];
    __syncthreads();

    int u = blockIdx.x * blockDim.x + threadIdx.x;
    if (u >= NN) return;

    bool act = (__ldg(depth + u) <= thr);
    if (!act) {
        if (out_final) {
            float4* o = reinterpret_cast<float4*>(out_final + (size_t)u * DIM);
            float4 z4 = make_float4(0.f, 0.f, 0.f, 0.f);
            o[0] = z4; o[1] = z4; o[2] = z4; o[3] = z4; o[4] = z4;
        }
        return;   // h unchanged, x was never dirtied for inactive nodes
    }

    const float* Wz = sW + 0 * DIM * DIM;
    const float* Uz = sW + 1 * DIM * DIM;
    const float* Wr = sW + 2 * DIM * DIM;
    const float* Ur = sW + 3 * DIM * DIM;
    const float* Wh = sW + 4 * DIM * DIM;
    const float* Uh = sW + 5 * DIM * DIM;
    const float* bz  = sB + 0 * DIM;
    const float* buz = sB + 1 * DIM;
    const float* br  = sB + 2 * DIM;
    const float* bur = sB + 3 * DIM;
    const float* bh  = sB + 4 * DIM;
    const float* buh = sB + 5 * DIM;

    float xv[DIM], hv[DIM];
    {
        float4* xp = reinterpret_cast<float4*>(g_x + (size_t)u * DIM);
        const float4* hp = reinterpret_cast<const float4*>(g_h + (size_t)u * DIM);
        float4 z4 = make_float4(0.f, 0.f, 0.f, 0.f);
#pragma unroll
        for (int k = 0; k < 5; k++) {
            float4 a = xp[k];
            xv[4*k+0] = a.x; xv[4*k+1] = a.y; xv[4*k+2] = a.z; xv[4*k+3] = a.w;
            float4 b = hp[k];
            hv[4*k+0] = b.x; hv[4*k+1] = b.y; hv[4*k+2] = b.z; hv[4*k+3] = b.w;
            if (clear_x) xp[k] = z4;   // fused re-zero for next iteration
        }
    }

    // r gate -> q = r * h
    float q[DIM];
#pragma unroll
    for (int j = 0; j < DIM; j++) {
        float s = br[j] + bur[j];
        const float4* wr = reinterpret_cast<const float4*>(Wr + j * DIM);
        const float4* ur = reinterpret_cast<const float4*>(Ur + j * DIM);
#pragma unroll
        for (int k = 0; k < 5; k++) {
            float4 w = wr[k], uu = ur[k];
            s += w.x  * xv[4*k+0] + w.y  * xv[4*k+1] + w.z  * xv[4*k+2] + w.w  * xv[4*k+3];
            s += uu.x * hv[4*k+0] + uu.y * hv[4*k+1] + uu.z * hv[4*k+2] + uu.w * hv[4*k+3];
        }
        q[j] = fsigmoid(s) * hv[j];
    }

    // z gate + candidate + blend
    float onew[DIM];
#pragma unroll
    for (int j = 0; j < DIM; j++) {
        float sz = bz[j] + buz[j];
        float sh = bh[j] + buh[j];
        const float4* wz = reinterpret_cast<const float4*>(Wz + j * DIM);
        const float4* uz = reinterpret_cast<const float4*>(Uz + j * DIM);
        const float4* wh = reinterpret_cast<const float4*>(Wh + j * DIM);
        const float4* uh = reinterpret_cast<const float4*>(Uh + j * DIM);
#pragma unroll
        for (int k = 0; k < 5; k++) {
            float4 a = wz[k], b = uz[k], c = wh[k], d = uh[k];
            sz += a.x * xv[4*k+0] + a.y * xv[4*k+1] + a.z * xv[4*k+2] + a.w * xv[4*k+3];
            sz += b.x * hv[4*k+0] + b.y * hv[4*k+1] + b.z * hv[4*k+2] + b.w * hv[4*k+3];
            sh += c.x * xv[4*k+0] + c.y * xv[4*k+1] + c.z * xv[4*k+2] + c.w * xv[4*k+3];
            sh += d.x * q [4*k+0] + d.y * q [4*k+1] + d.z * q [4*k+2] + d.w * q [4*k+3];
        }
        float z  = fsigmoid(sz);
        float hc = tanhf(sh);
        onew[j] = z * hv[j] + (1.f - z) * hc;
    }

    float* dst = out_final ? (out_final + (size_t)u * DIM) : (g_h + (size_t)u * DIM);
    float4* d4 = reinterpret_cast<float4*>(dst);
#pragma unroll
    for (int k = 0; k < 5; k++)
        d4[k] = make_float4(onew[4*k+0], onew[4*k+1], onew[4*k+2], onew[4*k+3]);
}

// ---------------------------------------------------------------------------
// launch
// ---------------------------------------------------------------------------
extern "C" void kernel_launch(void* const* d_in, const int* in_sizes, int n_in,
                              void* d_out, int out_size) {
    // Identify inputs by element count:
    //   N*DIM -> h, N -> node2depth, E (x2, in order) -> edge_src, edge_dst,
    //   400 (x6, in order) -> Wz,Uz,Wr,Ur,Wh,Uh, 20 (x6, in order) -> biases.
    const float* h_in = nullptr;
    const int*   depth = nullptr;
    const int*   esrc = nullptr;
    const int*   edst = nullptr;
    const float* Ws[6] = {};
    const float* Bs[6] = {};
    int wi = 0, bi = 0, ei = 0;
    for (int i = 0; i < n_in; i++) {
        int s = in_sizes[i];
        if (s == NN * DIM)      h_in  = (const float*)d_in[i];
        else if (s == NN)       depth = (const int*)d_in[i];
        else if (s == EE) {
            if (ei == 0) esrc = (const int*)d_in[i];
            else         edst = (const int*)d_in[i];
            ei++;
        }
        else if (s == DIM * DIM && wi < 6) Ws[wi++] = (const float*)d_in[i];
        else if (s == DIM      && bi < 6)  Bs[bi++] = (const float*)d_in[i];
    }

    WParams p;
    for (int m = 0; m < 6; m++) { p.W[m] = Ws[m]; p.B[m] = Bs[m]; }

    float* out = (float*)d_out;

    const int n4        = NN * DIM / 4;
    const int cb_init   = (n4 + 255) / 256;
    const int cb_comp   = (EE + CHUNK - 1) / CHUNK;
    const int cb_node   = (NN + 255) / 256;
    const int cb_scatter = 148 * 16;   // persistent grid-stride

    init_kernel<<<cb_init, 256>>>(h_in);
    compact_kernel<<<cb_comp, CTHREADS>>>(esrc, edst, depth);

    for (int i = 0; i < ITERS; i++) {
        int thr = ITERS - i;           // active: depth <= ITERS - i
        int nb  = ITERS - i;           // buckets used this iteration: 3,2,1
        scatter_kernel<<<cb_scatter, 256>>>(nb);
        gru_kernel<<<cb_node, 256>>>(depth, thr, p,
                                     (i == ITERS - 1) ? out : nullptr,
                                     (i < ITERS - 1) ? 1 : 0);
    }
}

// round 4
// speedup vs baseline: 1.2572x; 1.2572x over previous
#include <cuda_runtime.h>
#include <cstdint>

#define NN   200000
#define DIM  20
#define EE   6400000
#define ITERS 3

typedef unsigned long long ull;

// Persistent scratch (allocations banned; __device__ globals are the workaround)
__device__ __align__(16) float g_h[(size_t)NN * DIM];
__device__ __align__(16) float g_x[(size_t)NN * DIM];
__device__ unsigned char g_depth8[NN];
// Packed weight image: [m*200 + k*10 + jp] = (W_m[2jp][k], W_m[2jp+1][k]) for
// m in {Wz,Uz,Wr,Ur,Wh,Uh}; [1200..1209]=bz+buz pairs, [1210..1219]=br+bur,
// [1220..1229]=bh+buh.
__device__ __align__(16) float2 g_stage[1232];

// ---------------------------------------------------------------------------
// packed f32x2 helpers
// ---------------------------------------------------------------------------
#define FMA2(d, a, b, c) \
    asm("fma.rn.f32x2 %0, %1, %2, %3;" : "=l"(d) : "l"(a), "l"(b), "l"(c))
#define PACK2(d, lo, hi) \
    asm("mov.b64 %0, {%1, %2};" : "=l"(d) : "f"(lo), "f"(hi))
#define UNPACK2(lo, hi, s) \
    asm("mov.b64 {%0, %1}, %2;" : "=f"(lo), "=f"(hi) : "l"(s))

__device__ __forceinline__ float fsigmoid(float v) {
    return 1.f / (1.f + __expf(-v));
}
__device__ __forceinline__ float ftanh(float x) {
    // tanh(x) = 2*sigmoid(2x) - 1, via fast exp (accurate to a few ulp)
    return fmaf(2.f, 1.f / (1.f + __expf(-2.f * x)), -1.f);
}

// ---------------------------------------------------------------------------
// init: copy input h into scratch, zero x
// ---------------------------------------------------------------------------
__global__ void init_kernel(const float* __restrict__ h_in) {
    int i = blockIdx.x * blockDim.x + threadIdx.x;
    const int n4 = NN * DIM / 4;
    if (i < n4) {
        reinterpret_cast<float4*>(g_h)[i] = reinterpret_cast<const float4*>(h_in)[i];
        reinterpret_cast<float4*>(g_x)[i] = make_float4(0.f, 0.f, 0.f, 0.f);
    }
}

// ---------------------------------------------------------------------------
// prep: pack depth to uint8, pack weights/biases (transposed, pair-interleaved)
// ---------------------------------------------------------------------------
struct WParams {
    const float* W[6];   // Wz, Uz, Wr, Ur, Wh, Uh   ([DIM,DIM], row = out)
    const float* B[6];   // bz, buz, br, bur, bh, buh
};

__global__ void prep_kernel(const int* __restrict__ depth, WParams p) {
    int i = blockIdx.x * blockDim.x + threadIdx.x;
    if (i < NN)
        g_depth8[i] = (unsigned char)__ldg(depth + i);
    if (i < 1200) {
        int m  = i / 200;
        int r  = i % 200;
        int k  = r / 10;
        int jp = r % 10;
        const float* w = p.W[m];
        g_stage[m * 200 + k * 10 + jp] =
            make_float2(w[(2 * jp) * DIM + k], w[(2 * jp + 1) * DIM + k]);
    } else if (i < 1230) {
        int t  = i - 1200;
        int g  = t / 10;   // 0=z, 1=r, 2=h
        int jp = t % 10;
        const float* b0 = p.B[2 * g];
        const float* b1 = p.B[2 * g + 1];
        g_stage[1200 + g * 10 + jp] =
            make_float2(b0[2 * jp] + b1[2 * jp], b0[2 * jp + 1] + b1[2 * jp + 1]);
    } else if (i < 1232) {
        g_stage[i] = make_float2(0.f, 0.f);   // padding
    }
}

// ---------------------------------------------------------------------------
// scatter: x[dst] += h[src] for edges where both endpoints active
// ---------------------------------------------------------------------------
__device__ __forceinline__ void red_add_v4(float* p, float4 v) {
    unsigned long long ga = (unsigned long long)__cvta_generic_to_global((void*)p);
    asm volatile("red.global.add.v4.f32 [%0], {%1,%2,%3,%4};"
                 :: "l"(ga), "f"(v.x), "f"(v.y), "f"(v.z), "f"(v.w)
                 : "memory");
}

__global__ void scatter_kernel(const int* __restrict__ esrc,
                               const int* __restrict__ edst,
                               int thr) {
    int e = blockIdx.x * blockDim.x + threadIdx.x;
    if (e >= EE) return;
    int d = __ldg(edst + e);
    if (g_depth8[d] > thr) return;
    int s = __ldg(esrc + e);
    if (g_depth8[s] > thr) return;

    const float4* hp = reinterpret_cast<const float4*>(g_h + (size_t)s * DIM);
    float4 v0 = hp[0], v1 = hp[1], v2 = hp[2], v3 = hp[3], v4 = hp[4];

    float* xp = g_x + (size_t)d * DIM;
    red_add_v4(xp + 0,  v0);
    red_add_v4(xp + 4,  v1);
    red_add_v4(xp + 8,  v2);
    red_add_v4(xp + 12, v3);
    red_add_v4(xp + 16, v4);
}

// ---------------------------------------------------------------------------
// GRU update per node: packed f32x2 FMA, uniform-broadcast smem weight reads
// ---------------------------------------------------------------------------
__global__ void __launch_bounds__(128) gru_kernel(int thr,
                                                  float* __restrict__ out_final,
                                                  int clear_x) {
    // smem weight image (ull view of float2 pairs). Offsets (in ull units):
    // Wz=0, Uz=200, Wr=400, Ur=600, Wh=800, Uh=1000, Bz=1200, Br=1210, Bh=1220
    __shared__ __align__(16) ull sW[1232];
    {
        // g_stage: 1232 float2 = 9856 bytes = 616 float4
        const float4* src = reinterpret_cast<const float4*>(g_stage);
        float4* dst = reinterpret_cast<float4*>(sW);
        for (int t = threadIdx.x; t < 616; t += blockDim.x)
            dst[t] = src[t];
    }
    __syncthreads();

    int u = blockIdx.x * blockDim.x + threadIdx.x;
    if (u >= NN) return;

    if (g_depth8[u] > thr) {
        if (out_final) {
            float4* o = reinterpret_cast<float4*>(out_final + (size_t)u * DIM);
            float4 z4 = make_float4(0.f, 0.f, 0.f, 0.f);
            o[0] = z4; o[1] = z4; o[2] = z4; o[3] = z4; o[4] = z4;
        }
        return;   // h unchanged, x never dirtied for inactive nodes
    }

    // accumulators initialized with combined biases
    ull accz[10], accr[10], acch[10];
#pragma unroll
    for (int jp = 0; jp < 10; jp++) {
        accz[jp] = sW[1200 + jp];
        accr[jp] = sW[1210 + jp];
        acch[jp] = sW[1220 + jp];
    }

    // ---- Phase A: x contributions (Wz, Wr, Wh) ----
    {
        float xv[DIM];
        float4* xp = reinterpret_cast<float4*>(g_x + (size_t)u * DIM);
        float4 z4 = make_float4(0.f, 0.f, 0.f, 0.f);
#pragma unroll
        for (int k = 0; k < 5; k++) {
            float4 a = xp[k];
            xv[4*k+0] = a.x; xv[4*k+1] = a.y; xv[4*k+2] = a.z; xv[4*k+3] = a.w;
            if (clear_x) xp[k] = z4;   // fused re-zero for next iteration
        }
#pragma unroll
        for (int k = 0; k < DIM; k++) {
            ull b;
            PACK2(b, xv[k], xv[k]);
#pragma unroll
            for (int jp = 0; jp < 10; jp++) {
                FMA2(accz[jp], sW[       k * 10 + jp], b, accz[jp]);
                FMA2(accr[jp], sW[400  + k * 10 + jp], b, accr[jp]);
                FMA2(acch[jp], sW[800  + k * 10 + jp], b, acch[jp]);
            }
        }
    }

    // ---- Phase B: h contributions to z, r (Uz, Ur) ----
    float hv[DIM];
    {
        const float4* hp = reinterpret_cast<const float4*>(g_h + (size_t)u * DIM);
#pragma unroll
        for (int k = 0; k < 5; k++) {
            float4 a = hp[k];
            hv[4*k+0] = a.x; hv[4*k+1] = a.y; hv[4*k+2] = a.z; hv[4*k+3] = a.w;
        }
#pragma unroll
        for (int k = 0; k < DIM; k++) {
            ull b;
            PACK2(b, hv[k], hv[k]);
#pragma unroll
            for (int jp = 0; jp < 10; jp++) {
                FMA2(accz[jp], sW[200 + k * 10 + jp], b, accz[jp]);
                FMA2(accr[jp], sW[600 + k * 10 + jp], b, accr[jp]);
            }
        }
    }

    // ---- Phase C: r = sigmoid, q = r * h ----
    float q[DIM];
#pragma unroll
    for (int jp = 0; jp < 10; jp++) {
        float r0, r1;
        UNPACK2(r0, r1, accr[jp]);
        q[2*jp]     = fsigmoid(r0) * hv[2*jp];
        q[2*jp + 1] = fsigmoid(r1) * hv[2*jp + 1];
    }

    // ---- Phase D: q contributions to candidate (Uh) ----
#pragma unroll
    for (int k = 0; k < DIM; k++) {
        ull b;
        PACK2(b, q[k], q[k]);
#pragma unroll
        for (int jp = 0; jp < 10; jp++)
            FMA2(acch[jp], sW[1000 + k * 10 + jp], b, acch[jp]);
    }

    // ---- Phase E: gates, blend, store ----
    float o[DIM];
#pragma unroll
    for (int jp = 0; jp < 10; jp++) {
        float z0, z1, c0, c1;
        UNPACK2(z0, z1, accz[jp]);
        UNPACK2(c0, c1, acch[jp]);
        float zz0 = fsigmoid(z0), zz1 = fsigmoid(z1);
        float hc0 = ftanh(c0),    hc1 = ftanh(c1);
        o[2*jp]     = hc0 + zz0 * (hv[2*jp]     - hc0);
        o[2*jp + 1] = hc1 + zz1 * (hv[2*jp + 1] - hc1);
    }

    float* dstp = out_final ? (out_final + (size_t)u * DIM) : (g_h + (size_t)u * DIM);
    float4* d4 = reinterpret_cast<float4*>(dstp);
#pragma unroll
    for (int k = 0; k < 5; k++)
        d4[k] = make_float4(o[4*k+0], o[4*k+1], o[4*k+2], o[4*k+3]);
}

// ---------------------------------------------------------------------------
// launch
// ---------------------------------------------------------------------------
extern "C" void kernel_launch(void* const* d_in, const int* in_sizes, int n_in,
                              void* d_out, int out_size) {
    // Identify inputs by element count:
    //   N*DIM -> h, N -> node2depth, E (x2, in order) -> edge_src, edge_dst,
    //   400 (x6, in order) -> Wz,Uz,Wr,Ur,Wh,Uh, 20 (x6, in order) -> biases.
    const float* h_in = nullptr;
    const int*   depth = nullptr;
    const int*   esrc = nullptr;
    const int*   edst = nullptr;
    const float* Ws[6] = {};
    const float* Bs[6] = {};
    int wi = 0, bi = 0, ei = 0;
    for (int i = 0; i < n_in; i++) {
        int s = in_sizes[i];
        if (s == NN * DIM)      h_in  = (const float*)d_in[i];
        else if (s == NN)       depth = (const int*)d_in[i];
        else if (s == EE) {
            if (ei == 0) esrc = (const int*)d_in[i];
            else         edst = (const int*)d_in[i];
            ei++;
        }
        else if (s == DIM * DIM && wi < 6) Ws[wi++] = (const float*)d_in[i];
        else if (s == DIM      && bi < 6)  Bs[bi++] = (const float*)d_in[i];
    }

    WParams p;
    for (int m = 0; m < 6; m++) { p.W[m] = Ws[m]; p.B[m] = Bs[m]; }

    float* out = (float*)d_out;

    const int n4      = NN * DIM / 4;
    const int cb_init = (n4 + 255) / 256;
    const int cb_prep = (NN + 255) / 256;
    const int cb_edge = (EE + 255) / 256;
    const int cb_node = (NN + 127) / 128;

    init_kernel<<<cb_init, 256>>>(h_in);
    prep_kernel<<<cb_prep, 256>>>(depth, p);

    for (int i = 0; i < ITERS; i++) {
        int thr = ITERS - i;   // active: depth + i <= ITERS  <=>  depth <= ITERS - i
        scatter_kernel<<<cb_edge, 256>>>(esrc, edst, thr);
        gru_kernel<<<cb_node, 128>>>(thr,
                                     (i == ITERS - 1) ? out : nullptr,
                                     (i < ITERS - 1) ? 1 : 0);
    }
}

// round 5
// speedup vs baseline: 1.6403x; 1.3048x over previous
#include <cuda_runtime.h>
#include <cstdint>

#define NN    200000
#define DIM   20
#define EE    6400000
#define ITERS 3
#define NBLK  ((NN + 255) / 256)   // 782 scan blocks
#define LIFE_DROP 255

typedef unsigned long long ull;

// Persistent scratch (allocations banned; __device__ globals are the workaround)
__device__ __align__(16) float g_h[(size_t)NN * DIM];
__device__ __align__(16) float g_x[(size_t)NN * DIM];
__device__ unsigned char g_depth8[NN];
__device__ __align__(16) float2 g_stage[1232];
// CSR-by-dst machinery
__device__ int g_deg[NN];
__device__ int g_cur[NN];
__device__ int g_off[NN + 1];
__device__ int g_bsum[1024];
__device__ int g_boff[1024];
__device__ unsigned char g_elife[EE];
__device__ int g_csr[EE];

// ---------------------------------------------------------------------------
// packed f32x2 helpers
// ---------------------------------------------------------------------------
#define FMA2(d, a, b, c) \
    asm("fma.rn.f32x2 %0, %1, %2, %3;" : "=l"(d) : "l"(a), "l"(b), "l"(c))
#define PACK2(d, lo, hi) \
    asm("mov.b64 %0, {%1, %2};" : "=l"(d) : "f"(lo), "f"(hi))
#define UNPACK2(lo, hi, s) \
    asm("mov.b64 {%0, %1}, %2;" : "=f"(lo), "=f"(hi) : "l"(s))

__device__ __forceinline__ float fsigmoid(float v) {
    return 1.f / (1.f + __expf(-v));
}
__device__ __forceinline__ float ftanh(float x) {
    return fmaf(2.f, 1.f / (1.f + __expf(-2.f * x)), -1.f);
}

// ---------------------------------------------------------------------------
// init: copy h into scratch, zero degree counters
// ---------------------------------------------------------------------------
__global__ void init_kernel(const float* __restrict__ h_in) {
    int i = blockIdx.x * blockDim.x + threadIdx.x;
    const int n4 = NN * DIM / 4;
    if (i < n4)
        reinterpret_cast<float4*>(g_h)[i] = reinterpret_cast<const float4*>(h_in)[i];
    if (i < NN)
        g_deg[i] = 0;
}

// ---------------------------------------------------------------------------
// prep: pack depth to uint8, pack weights/biases (transposed, pair-interleaved)
// ---------------------------------------------------------------------------
struct WParams {
    const float* W[6];   // Wz, Uz, Wr, Ur, Wh, Uh   ([DIM,DIM], row = out)
    const float* B[6];   // bz, buz, br, bur, bh, buh
};

__global__ void prep_kernel(const int* __restrict__ depth, WParams p) {
    int i = blockIdx.x * blockDim.x + threadIdx.x;
    if (i < NN)
        g_depth8[i] = (unsigned char)__ldg(depth + i);
    if (i < 1200) {
        int m  = i / 200;
        int r  = i % 200;
        int k  = r / 10;
        int jp = r % 10;
        const float* w = p.W[m];
        g_stage[m * 200 + k * 10 + jp] =
            make_float2(w[(2 * jp) * DIM + k], w[(2 * jp + 1) * DIM + k]);
    } else if (i < 1230) {
        int t  = i - 1200;
        int g  = t / 10;   // 0=z, 1=r, 2=h
        int jp = t % 10;
        const float* b0 = p.B[2 * g];
        const float* b1 = p.B[2 * g + 1];
        g_stage[1200 + g * 10 + jp] =
            make_float2(b0[2 * jp] + b1[2 * jp], b0[2 * jp + 1] + b1[2 * jp + 1]);
    } else if (i < 1232) {
        g_stage[i] = make_float2(0.f, 0.f);
    }
}

// ---------------------------------------------------------------------------
// CSR build: histogram -> scan -> fill
// ---------------------------------------------------------------------------
__global__ void hist_kernel(const int* __restrict__ esrc,
                            const int* __restrict__ edst) {
    int e = blockIdx.x * blockDim.x + threadIdx.x;
    if (e >= EE) return;
    int s = __ldg(esrc + e);
    int d = __ldg(edst + e);
    int maxd = max((int)g_depth8[s], (int)g_depth8[d]);
    unsigned char life = LIFE_DROP;
    if (maxd <= 3) {
        life = (unsigned char)(3 - maxd);   // active for iters 0..life
        atomicAdd(&g_deg[d], 1);
    }
    g_elife[e] = life;
}

__global__ void scanA_kernel() {   // per-block sums of g_deg
    __shared__ int sm[256];
    int i = blockIdx.x * 256 + threadIdx.x;
    int v = (i < NN) ? g_deg[i] : 0;
    sm[threadIdx.x] = v;
    __syncthreads();
    for (int off = 128; off > 0; off >>= 1) {
        if (threadIdx.x < off) sm[threadIdx.x] += sm[threadIdx.x + off];
        __syncthreads();
    }
    if (threadIdx.x == 0) g_bsum[blockIdx.x] = sm[0];
}

__global__ void scanB_kernel() {   // single block: exclusive scan of block sums
    __shared__ int sm[1024];
    int t = threadIdx.x;
    int v = (t < NBLK) ? g_bsum[t] : 0;
    sm[t] = v;
    __syncthreads();
    for (int off = 1; off < 1024; off <<= 1) {
        int add = (t >= off) ? sm[t - off] : 0;
        __syncthreads();
        sm[t] += add;
        __syncthreads();
    }
    if (t < NBLK) g_boff[t] = sm[t] - v;
}

__global__ void scanC_kernel() {   // per-element exclusive offsets + cursors
    __shared__ int sm[256];
    int i = blockIdx.x * 256 + threadIdx.x;
    int v = (i < NN) ? g_deg[i] : 0;
    sm[threadIdx.x] = v;
    __syncthreads();
    for (int off = 1; off < 256; off <<= 1) {
        int add = (threadIdx.x >= off) ? sm[threadIdx.x - off] : 0;
        __syncthreads();
        sm[threadIdx.x] += add;
        __syncthreads();
    }
    if (i < NN) {
        int base = g_boff[blockIdx.x];
        int excl = sm[threadIdx.x] - v;
        g_off[i] = base + excl;
        g_cur[i] = base + excl;
        if (i == NN - 1) g_off[NN] = base + sm[threadIdx.x];
    }
}

__global__ void fill_kernel(const int* __restrict__ esrc,
                            const int* __restrict__ edst) {
    int e = blockIdx.x * blockDim.x + threadIdx.x;
    if (e >= EE) return;
    unsigned char life = g_elife[e];
    if (life == LIFE_DROP) return;
    int d = __ldg(edst + e);
    int pos = atomicAdd(&g_cur[d], 1);
    g_csr[pos] = __ldg(esrc + e) | ((int)life << 18);
}

// ---------------------------------------------------------------------------
// gather: x[u] = sum over CSR entries with life >= iter (5 lanes per node)
// ---------------------------------------------------------------------------
__global__ void gather_kernel(int iter, int thr) {
    int lane = threadIdx.x & 31;
    if (lane >= 30) return;                        // 6 groups of 5 per warp
    int warp = (blockIdx.x * blockDim.x + threadIdx.x) >> 5;
    int u = warp * 6 + lane / 5;
    if (u >= NN) return;
    if (g_depth8[u] > thr) return;                 // inactive dst: x never read
    int c = lane % 5;                              // float4 chunk owned

    int beg = g_off[u], end = g_off[u + 1];
    float4 acc = make_float4(0.f, 0.f, 0.f, 0.f);
    for (int e = beg; e < end; e++) {
        int entry = g_csr[e];
        if ((entry >> 18) < iter) continue;        // edge expired
        int s = entry & 0x3FFFF;
        float4 v = __ldg(reinterpret_cast<const float4*>(g_h + (size_t)s * DIM) + c);
        acc.x += v.x; acc.y += v.y; acc.z += v.z; acc.w += v.w;
    }
    reinterpret_cast<float4*>(g_x + (size_t)u * DIM)[c] = acc;
}

// ---------------------------------------------------------------------------
// GRU update per node: packed f32x2 FMA, uniform-broadcast smem weight reads
// ---------------------------------------------------------------------------
__global__ void __launch_bounds__(128) gru_kernel(int thr,
                                                  float* __restrict__ out_final) {
    // smem weight image (ull view). Offsets (ull units):
    // Wz=0, Uz=200, Wr=400, Ur=600, Wh=800, Uh=1000, Bz=1200, Br=1210, Bh=1220
    __shared__ __align__(16) ull sW[1232];
    {
        const float4* src = reinterpret_cast<const float4*>(g_stage);
        float4* dst = reinterpret_cast<float4*>(sW);
        for (int t = threadIdx.x; t < 616; t += blockDim.x)
            dst[t] = src[t];
    }
    __syncthreads();

    int u = blockIdx.x * blockDim.x + threadIdx.x;
    if (u >= NN) return;

    if (g_depth8[u] > thr) {
        if (out_final) {
            float4* o = reinterpret_cast<float4*>(out_final + (size_t)u * DIM);
            float4 z4 = make_float4(0.f, 0.f, 0.f, 0.f);
            o[0] = z4; o[1] = z4; o[2] = z4; o[3] = z4; o[4] = z4;
        }
        return;
    }

    ull accz[10], accr[10], acch[10];
#pragma unroll
    for (int jp = 0; jp < 10; jp++) {
        accz[jp] = sW[1200 + jp];
        accr[jp] = sW[1210 + jp];
        acch[jp] = sW[1220 + jp];
    }

    // ---- Phase A: x contributions (Wz, Wr, Wh) ----
    {
        float xv[DIM];
        const float4* xp = reinterpret_cast<const float4*>(g_x + (size_t)u * DIM);
#pragma unroll
        for (int k = 0; k < 5; k++) {
            float4 a = xp[k];
            xv[4*k+0] = a.x; xv[4*k+1] = a.y; xv[4*k+2] = a.z; xv[4*k+3] = a.w;
        }
#pragma unroll
        for (int k = 0; k < DIM; k++) {
            ull b;
            PACK2(b, xv[k], xv[k]);
#pragma unroll
            for (int jp = 0; jp < 10; jp++) {
                FMA2(accz[jp], sW[       k * 10 + jp], b, accz[jp]);
                FMA2(accr[jp], sW[400  + k * 10 + jp], b, accr[jp]);
                FMA2(acch[jp], sW[800  + k * 10 + jp], b, acch[jp]);
            }
        }
    }

    // ---- Phase B: h contributions to z, r (Uz, Ur) ----
    float hv[DIM];
    {
        const float4* hp = reinterpret_cast<const float4*>(g_h + (size_t)u * DIM);
#pragma unroll
        for (int k = 0; k < 5; k++) {
            float4 a = hp[k];
            hv[4*k+0] = a.x; hv[4*k+1] = a.y; hv[4*k+2] = a.z; hv[4*k+3] = a.w;
        }
#pragma unroll
        for (int k = 0; k < DIM; k++) {
            ull b;
            PACK2(b, hv[k], hv[k]);
#pragma unroll
            for (int jp = 0; jp < 10; jp++) {
                FMA2(accz[jp], sW[200 + k * 10 + jp], b, accz[jp]);
                FMA2(accr[jp], sW[600 + k * 10 + jp], b, accr[jp]);
            }
        }
    }

    // ---- Phase C: r = sigmoid, q = r * h ----
    float q[DIM];
#pragma unroll
    for (int jp = 0; jp < 10; jp++) {
        float r0, r1;
        UNPACK2(r0, r1, accr[jp]);
        q[2*jp]     = fsigmoid(r0) * hv[2*jp];
        q[2*jp + 1] = fsigmoid(r1) * hv[2*jp + 1];
    }

    // ---- Phase D: q contributions to candidate (Uh) ----
#pragma unroll
    for (int k = 0; k < DIM; k++) {
        ull b;
        PACK2(b, q[k], q[k]);
#pragma unroll
        for (int jp = 0; jp < 10; jp++)
            FMA2(acch[jp], sW[1000 + k * 10 + jp], b, acch[jp]);
    }

    // ---- Phase E: gates, blend, store ----
    float o[DIM];
#pragma unroll
    for (int jp = 0; jp < 10; jp++) {
        float z0, z1, c0, c1;
        UNPACK2(z0, z1, accz[jp]);
        UNPACK2(c0, c1, acch[jp]);
        float zz0 = fsigmoid(z0), zz1 = fsigmoid(z1);
        float hc0 = ftanh(c0),    hc1 = ftanh(c1);
        o[2*jp]     = hc0 + zz0 * (hv[2*jp]     - hc0);
        o[2*jp + 1] = hc1 + zz1 * (hv[2*jp + 1] - hc1);
    }

    float* dstp = out_final ? (out_final + (size_t)u * DIM) : (g_h + (size_t)u * DIM);
    float4* d4 = reinterpret_cast<float4*>(dstp);
#pragma unroll
    for (int k = 0; k < 5; k++)
        d4[k] = make_float4(o[4*k+0], o[4*k+1], o[4*k+2], o[4*k+3]);
}

// ---------------------------------------------------------------------------
// launch
// ---------------------------------------------------------------------------
extern "C" void kernel_launch(void* const* d_in, const int* in_sizes, int n_in,
                              void* d_out, int out_size) {
    const float* h_in = nullptr;
    const int*   depth = nullptr;
    const int*   esrc = nullptr;
    const int*   edst = nullptr;
    const float* Ws[6] = {};
    const float* Bs[6] = {};
    int wi = 0, bi = 0, ei = 0;
    for (int i = 0; i < n_in; i++) {
        int s = in_sizes[i];
        if (s == NN * DIM)      h_in  = (const float*)d_in[i];
        else if (s == NN)       depth = (const int*)d_in[i];
        else if (s == EE) {
            if (ei == 0) esrc = (const int*)d_in[i];
            else         edst = (const int*)d_in[i];
            ei++;
        }
        else if (s == DIM * DIM && wi < 6) Ws[wi++] = (const float*)d_in[i];
        else if (s == DIM      && bi < 6)  Bs[bi++] = (const float*)d_in[i];
    }

    WParams p;
    for (int m = 0; m < 6; m++) { p.W[m] = Ws[m]; p.B[m] = Bs[m]; }

    float* out = (float*)d_out;

    const int n4      = NN * DIM / 4;
    const int cb_init = (n4 + 255) / 256;
    const int cb_prep = (NN + 255) / 256;
    const int cb_edge = (EE + 255) / 256;
    const int cb_node = (NN + 127) / 128;
    // gather: 48 nodes per 256-thread block (8 warps x 6 nodes)
    const int cb_gath = (NN + 47) / 48;

    init_kernel<<<cb_init, 256>>>(h_in);
    prep_kernel<<<cb_prep, 256>>>(depth, p);
    hist_kernel<<<cb_edge, 256>>>(esrc, edst);
    scanA_kernel<<<NBLK, 256>>>();
    scanB_kernel<<<1, 1024>>>();
    scanC_kernel<<<NBLK, 256>>>();
    fill_kernel<<<cb_edge, 256>>>(esrc, edst);

    for (int i = 0; i < ITERS; i++) {
        int thr = ITERS - i;   // active: depth <= ITERS - i
        gather_kernel<<<cb_gath, 256>>>(i, thr);
        gru_kernel<<<cb_node, 128>>>(thr, (i == ITERS - 1) ? out : nullptr);
    }
}

// round 6
// speedup vs baseline: 1.7511x; 1.0675x over previous
#include <cuda_runtime.h>
#include <cstdint>

#define NN    200000
#define DIM   20
#define EE    6400000
#define ITERS 3
#define NBLK  ((NN + 255) / 256)   // 782 scan blocks
#define LIFE_DROP 255

typedef unsigned long long ull;

// Persistent scratch (allocations banned; __device__ globals are the workaround)
__device__ __align__(16) float g_h[(size_t)NN * DIM];
__device__ __align__(16) float g_x[(size_t)NN * DIM];
__device__ unsigned char g_depth8[NN];
__device__ __align__(16) float2 g_stage[1232];
// CSR-by-dst machinery
__device__ int g_deg[NN];
__device__ int g_cur[NN];
__device__ int g_off[NN + 1];
__device__ int g_bsum[1024];
__device__ int g_boff[1024];
__device__ unsigned char g_elife[EE];
__device__ int g_csr[EE];

// ---------------------------------------------------------------------------
// packed f32x2 helpers
// ---------------------------------------------------------------------------
#define FMA2(d, a, b, c) \
    asm("fma.rn.f32x2 %0, %1, %2, %3;" : "=l"(d) : "l"(a), "l"(b), "l"(c))
#define PACK2(d, lo, hi) \
    asm("mov.b64 %0, {%1, %2};" : "=l"(d) : "f"(lo), "f"(hi))
#define UNPACK2(lo, hi, s) \
    asm("mov.b64 {%0, %1}, %2;" : "=f"(lo), "=f"(hi) : "l"(s))

__device__ __forceinline__ float fsigmoid(float v) {
    return 1.f / (1.f + __expf(-v));
}
__device__ __forceinline__ float ftanh(float x) {
    return fmaf(2.f, 1.f / (1.f + __expf(-2.f * x)), -1.f);
}

// ---------------------------------------------------------------------------
// init: copy h into scratch, zero degree counters
// ---------------------------------------------------------------------------
__global__ void init_kernel(const float* __restrict__ h_in) {
    int i = blockIdx.x * blockDim.x + threadIdx.x;
    const int n4 = NN * DIM / 4;
    if (i < n4)
        reinterpret_cast<float4*>(g_h)[i] = reinterpret_cast<const float4*>(h_in)[i];
    if (i < NN)
        g_deg[i] = 0;
}

// ---------------------------------------------------------------------------
// prep: pack depth to uint8, pack weights/biases (transposed, pair-interleaved)
// ---------------------------------------------------------------------------
struct WParams {
    const float* W[6];   // Wz, Uz, Wr, Ur, Wh, Uh   ([DIM,DIM], row = out)
    const float* B[6];   // bz, buz, br, bur, bh, buh
};

__global__ void prep_kernel(const int* __restrict__ depth, WParams p) {
    int i = blockIdx.x * blockDim.x + threadIdx.x;
    if (i < NN)
        g_depth8[i] = (unsigned char)__ldg(depth + i);
    if (i < 1200) {
        int m  = i / 200;
        int r  = i % 200;
        int k  = r / 10;
        int jp = r % 10;
        const float* w = p.W[m];
        g_stage[m * 200 + k * 10 + jp] =
            make_float2(w[(2 * jp) * DIM + k], w[(2 * jp + 1) * DIM + k]);
    } else if (i < 1230) {
        int t  = i - 1200;
        int g  = t / 10;   // 0=z, 1=r, 2=h
        int jp = t % 10;
        const float* b0 = p.B[2 * g];
        const float* b1 = p.B[2 * g + 1];
        g_stage[1200 + g * 10 + jp] =
            make_float2(b0[2 * jp] + b1[2 * jp], b0[2 * jp + 1] + b1[2 * jp + 1]);
    } else if (i < 1232) {
        g_stage[i] = make_float2(0.f, 0.f);
    }
}

// ---------------------------------------------------------------------------
// CSR build: histogram -> scan -> fill
// ---------------------------------------------------------------------------
__global__ void hist_kernel(const int* __restrict__ esrc,
                            const int* __restrict__ edst) {
    int e = blockIdx.x * blockDim.x + threadIdx.x;
    if (e >= EE) return;
    int s = __ldg(esrc + e);
    int d = __ldg(edst + e);
    int maxd = max((int)g_depth8[s], (int)g_depth8[d]);
    unsigned char life = LIFE_DROP;
    if (maxd <= 3) {
        life = (unsigned char)(3 - maxd);   // active for iters 0..life
        atomicAdd(&g_deg[d], 1);
    }
    g_elife[e] = life;
}

__global__ void scanA_kernel() {   // per-block sums of g_deg
    __shared__ int sm[256];
    int i = blockIdx.x * 256 + threadIdx.x;
    int v = (i < NN) ? g_deg[i] : 0;
    sm[threadIdx.x] = v;
    __syncthreads();
    for (int off = 128; off > 0; off >>= 1) {
        if (threadIdx.x < off) sm[threadIdx.x] += sm[threadIdx.x + off];
        __syncthreads();
    }
    if (threadIdx.x == 0) g_bsum[blockIdx.x] = sm[0];
}

__global__ void scanB_kernel() {   // single block: exclusive scan of block sums
    __shared__ int sm[1024];
    int t = threadIdx.x;
    int v = (t < NBLK) ? g_bsum[t] : 0;
    sm[t] = v;
    __syncthreads();
    for (int off = 1; off < 1024; off <<= 1) {
        int add = (t >= off) ? sm[t - off] : 0;
        __syncthreads();
        sm[t] += add;
        __syncthreads();
    }
    if (t < NBLK) g_boff[t] = sm[t] - v;
}

__global__ void scanC_kernel() {   // per-element exclusive offsets + cursors
    __shared__ int sm[256];
    int i = blockIdx.x * 256 + threadIdx.x;
    int v = (i < NN) ? g_deg[i] : 0;
    sm[threadIdx.x] = v;
    __syncthreads();
    for (int off = 1; off < 256; off <<= 1) {
        int add = (threadIdx.x >= off) ? sm[threadIdx.x - off] : 0;
        __syncthreads();
        sm[threadIdx.x] += add;
        __syncthreads();
    }
    if (i < NN) {
        int base = g_boff[blockIdx.x];
        int excl = sm[threadIdx.x] - v;
        g_off[i] = base + excl;
        g_cur[i] = base + excl;
        if (i == NN - 1) g_off[NN] = base + sm[threadIdx.x];
    }
}

__global__ void fill_kernel(const int* __restrict__ esrc,
                            const int* __restrict__ edst) {
    int e = blockIdx.x * blockDim.x + threadIdx.x;
    if (e >= EE) return;
    unsigned char life = g_elife[e];
    if (life == LIFE_DROP) return;
    int d = __ldg(edst + e);
    int pos = atomicAdd(&g_cur[d], 1);
    g_csr[pos] = __ldg(esrc + e) | ((int)life << 18);
}

// ---------------------------------------------------------------------------
// gather: x[u] = sum over CSR entries with life >= iter (5 lanes per node)
// ---------------------------------------------------------------------------
__global__ void gather_kernel(int iter, int thr) {
    int lane = threadIdx.x & 31;
    if (lane >= 30) return;                        // 6 groups of 5 per warp
    int warp = (blockIdx.x * blockDim.x + threadIdx.x) >> 5;
    int u = warp * 6 + lane / 5;
    if (u >= NN) return;
    if (g_depth8[u] > thr) return;                 // inactive dst: x never read
    int c = lane % 5;                              // float4 chunk owned

    int beg = g_off[u], end = g_off[u + 1];
    float4 acc = make_float4(0.f, 0.f, 0.f, 0.f);
    for (int e = beg; e < end; e++) {
        int entry = g_csr[e];
        if ((entry >> 18) < iter) continue;        // edge expired
        int s = entry & 0x3FFFF;
        float4 v = __ldg(reinterpret_cast<const float4*>(g_h + (size_t)s * DIM) + c);
        acc.x += v.x; acc.y += v.y; acc.z += v.z; acc.w += v.w;
    }
    reinterpret_cast<float4*>(g_x + (size_t)u * DIM)[c] = acc;
}

// ---------------------------------------------------------------------------
// GRU update: 2 threads per node. Thread `half` computes output pairs
// P = half*5 + jp (jp=0..4), i.e. outputs [10*half, 10*half+10).
// q vector exchanged between the pair via shfl.xor(1).
// ---------------------------------------------------------------------------
__global__ void __launch_bounds__(256) gru_kernel(int thr,
                                                  float* __restrict__ out_final) {
    // smem weight image (ull view). Offsets (ull units):
    // Wz=0, Uz=200, Wr=400, Ur=600, Wh=800, Uh=1000, Bz=1200, Br=1210, Bh=1220
    __shared__ __align__(16) ull sW[1232];
    {
        const float4* src = reinterpret_cast<const float4*>(g_stage);
        float4* dst = reinterpret_cast<float4*>(sW);
        for (int t = threadIdx.x; t < 616; t += blockDim.x)
            dst[t] = src[t];
    }
    __syncthreads();

    int gid  = blockIdx.x * blockDim.x + threadIdx.x;
    int u    = gid >> 1;
    int half = gid & 1;
    bool inb = (u < NN);
    bool act = inb && (g_depth8[u] <= thr);
    unsigned mask = __ballot_sync(0xFFFFFFFFu, act);

    if (!act) {
        if (inb && out_final) {
            float2* o = reinterpret_cast<float2*>(out_final + (size_t)u * DIM + 10 * half);
            float2 z2 = make_float2(0.f, 0.f);
#pragma unroll
            for (int k = 0; k < 5; k++) o[k] = z2;
        }
        return;
    }

    const int base = half * 5;   // pair index offset

    ull accz[5], accr[5], acch[5];
#pragma unroll
    for (int jp = 0; jp < 5; jp++) {
        accz[jp] = sW[1200 + base + jp];
        accr[jp] = sW[1210 + base + jp];
        acch[jp] = sW[1220 + base + jp];
    }

    // load x and h rows (both threads of the pair read the same rows; L1 hit)
    float xv[DIM], hv[DIM];
    {
        const float4* xp = reinterpret_cast<const float4*>(g_x + (size_t)u * DIM);
        const float4* hp = reinterpret_cast<const float4*>(g_h + (size_t)u * DIM);
#pragma unroll
        for (int k = 0; k < 5; k++) {
            float4 a = xp[k];
            xv[4*k+0] = a.x; xv[4*k+1] = a.y; xv[4*k+2] = a.z; xv[4*k+3] = a.w;
            float4 b = hp[k];
            hv[4*k+0] = b.x; hv[4*k+1] = b.y; hv[4*k+2] = b.z; hv[4*k+3] = b.w;
        }
    }

    // ---- Phase A: x contributions (Wz, Wr, Wh) ----
#pragma unroll
    for (int k = 0; k < DIM; k++) {
        ull b;
        PACK2(b, xv[k], xv[k]);
#pragma unroll
        for (int jp = 0; jp < 5; jp++) {
            FMA2(accz[jp], sW[      k * 10 + base + jp], b, accz[jp]);
            FMA2(accr[jp], sW[400 + k * 10 + base + jp], b, accr[jp]);
            FMA2(acch[jp], sW[800 + k * 10 + base + jp], b, acch[jp]);
        }
    }

    // ---- Phase B: h contributions to z, r (Uz, Ur) ----
#pragma unroll
    for (int k = 0; k < DIM; k++) {
        ull b;
        PACK2(b, hv[k], hv[k]);
#pragma unroll
        for (int jp = 0; jp < 5; jp++) {
            FMA2(accz[jp], sW[200 + k * 10 + base + jp], b, accz[jp]);
            FMA2(accr[jp], sW[600 + k * 10 + base + jp], b, accr[jp]);
        }
    }

    // ---- Phase C: r = sigmoid, qa = r * h (my 10 outputs) ----
    float qa[10];
#pragma unroll
    for (int jp = 0; jp < 5; jp++) {
        float r0, r1;
        UNPACK2(r0, r1, accr[jp]);
        int oidx = 2 * (base + jp);
        qa[2*jp]     = fsigmoid(r0) * hv[oidx];
        qa[2*jp + 1] = fsigmoid(r1) * hv[oidx + 1];
    }

    // exchange q halves with partner (lane ^ 1)
    float q[DIM];
#pragma unroll
    for (int t = 0; t < 10; t++) {
        q[10 * half + t]       = qa[t];
        q[10 * (1 - half) + t] = __shfl_xor_sync(mask, qa[t], 1);
    }

    // ---- Phase D: q contributions to candidate (Uh) ----
#pragma unroll
    for (int k = 0; k < DIM; k++) {
        ull b;
        PACK2(b, q[k], q[k]);
#pragma unroll
        for (int jp = 0; jp < 5; jp++)
            FMA2(acch[jp], sW[1000 + k * 10 + base + jp], b, acch[jp]);
    }

    // ---- Phase E: gates, blend, store my 10 outputs ----
    float* dstp = out_final ? (out_final + (size_t)u * DIM) : (g_h + (size_t)u * DIM);
    float2* d2 = reinterpret_cast<float2*>(dstp + 10 * half);
#pragma unroll
    for (int jp = 0; jp < 5; jp++) {
        float z0, z1, c0, c1;
        UNPACK2(z0, z1, accz[jp]);
        UNPACK2(c0, c1, acch[jp]);
        int oidx = 2 * (base + jp);
        float zz0 = fsigmoid(z0), zz1 = fsigmoid(z1);
        float hc0 = ftanh(c0),    hc1 = ftanh(c1);
        d2[jp] = make_float2(hc0 + zz0 * (hv[oidx]     - hc0),
                             hc1 + zz1 * (hv[oidx + 1] - hc1));
    }
}

// ---------------------------------------------------------------------------
// launch
// ---------------------------------------------------------------------------
extern "C" void kernel_launch(void* const* d_in, const int* in_sizes, int n_in,
                              void* d_out, int out_size) {
    const float* h_in = nullptr;
    const int*   depth = nullptr;
    const int*   esrc = nullptr;
    const int*   edst = nullptr;
    const float* Ws[6] = {};
    const float* Bs[6] = {};
    int wi = 0, bi = 0, ei = 0;
    for (int i = 0; i < n_in; i++) {
        int s = in_sizes[i];
        if (s == NN * DIM)      h_in  = (const float*)d_in[i];
        else if (s == NN)       depth = (const int*)d_in[i];
        else if (s == EE) {
            if (ei == 0) esrc = (const int*)d_in[i];
            else         edst = (const int*)d_in[i];
            ei++;
        }
        else if (s == DIM * DIM && wi < 6) Ws[wi++] = (const float*)d_in[i];
        else if (s == DIM      && bi < 6)  Bs[bi++] = (const float*)d_in[i];
    }

    WParams p;
    for (int m = 0; m < 6; m++) { p.W[m] = Ws[m]; p.B[m] = Bs[m]; }

    float* out = (float*)d_out;

    const int n4      = NN * DIM / 4;
    const int cb_init = (n4 + 255) / 256;
    const int cb_prep = (NN + 255) / 256;
    const int cb_edge = (EE + 255) / 256;
    const int cb_node2 = (2 * NN + 255) / 256;   // 2 threads per node
    // gather: 48 nodes per 256-thread block (8 warps x 6 nodes)
    const int cb_gath = (NN + 47) / 48;

    init_kernel<<<cb_init, 256>>>(h_in);
    prep_kernel<<<cb_prep, 256>>>(depth, p);
    hist_kernel<<<cb_edge, 256>>>(esrc, edst);
    scanA_kernel<<<NBLK, 256>>>();
    scanB_kernel<<<1, 1024>>>();
    scanC_kernel<<<NBLK, 256>>>();
    fill_kernel<<<cb_edge, 256>>>(esrc, edst);

    for (int i = 0; i < ITERS; i++) {
        int thr = ITERS - i;   // active: depth <= ITERS - i
        gather_kernel<<<cb_gath, 256>>>(i, thr);
        gru_kernel<<<cb_node2, 256>>>(thr, (i == ITERS - 1) ? out : nullptr);
    }
}